// round 17
// baseline (speedup 1.0000x reference)
#include <cuda_runtime.h>

// Fused beam reorder + suffix append for KV cache.  [FINAL — converged]
// Shapes: L=8, G=128, NH=8, T=128, HD=64, fp32.
//   out_k[l,g,h,t,:] = (t==pos) ? k_new[l,g,h,0,:] : k_buf[l,beam[g],h,t,:]
//   out_v analogous. Output = [k ; v] concatenated.
//
// float4 (16B) units: NEL4 = 2^24 per buffer; beam stride = 2^14.
//   t=(j>>4)&127; g=(j>>14)&127; gather src = j + (beam[g]-g)<<14
//   append src = ((j>>11)<<4)|(j&15)   ({k,v}_new is [L,G,NH,1,HD])
//
// Convergence evidence (R1-R16, 4 repeated measurements of this source:
// kernel 130.1/130.5/130.7 us + one 136.3 low-clock outlier):
//  - Compulsory DRAM traffic ≈ 836 MB (512 MB writes + unique-beam reads,
//    E[unique]≈81/128; L2 dedups duplicates given full-grid concurrency —
//    persistent pipelining broke this, +14% traffic, R8).
//  - Healthy-run ceiling 6.5-6.58 TB/s invariant across ILP{1,4,8}, widths
//    {128b,256b}, block sizes {256,512,1024}, cache policies, beam-sorted
//    ordering, K+V fusion. Floor ≈ 128 us; this kernel is within 1.6%.
//  - Config: ILP4 128-bit, 256-thr, front-batched loads (MLP_p1=4, the one
//    real lever: R1->R2 gave -10%), default-policy gathers (preserve L2
//    dedup), .cs streaming stores. 24 regs, occ ~84%.
//
// Block = 256 thr x ILP 4 = 1024 contiguous float4, 1024-aligned.
// 1024 | 2^14 => g, is_v, and the beam delta are uniform per block.

static constexpr unsigned NEL4  = 1u << 24;      // float4s per buffer
static constexpr unsigned TOTAL = 1u << 25;      // k + v
static constexpr int      ILP   = 4;
static constexpr int      THREADS = 256;

__global__ void __launch_bounds__(THREADS, 8)
beam_reorder_append_kernel(const float4* __restrict__ kb,
                           const float4* __restrict__ vb,
                           const float4* __restrict__ kn,
                           const float4* __restrict__ vn,
                           const int*    __restrict__ beam,
                           const int*    __restrict__ posp,
                           float4*       __restrict__ out)
{
    const unsigned base = blockIdx.x * (THREADS * ILP);   // 1024-aligned
    const bool is_v = base >= NEL4;                       // uniform per block
    const unsigned jbase = base & (NEL4 - 1);

    const int pos = *posp;                                // L1-hit, uniform
    const unsigned g = (jbase >> 14) & 127;               // uniform per block
    const unsigned delta = ((unsigned)(beam[g] - (int)g)) << 14;  // uniform

    const float4* __restrict__ buf  = is_v ? vb : kb;
    const float4* __restrict__ nbuf = is_v ? vn : kn;

    float4 r[ILP];

    // Front-batch all 4 independent 128-bit loads (MLP_p1 = 4).
    // Default cache policy: duplicate-beam lines stay L2-resident for dedup.
    #pragma unroll
    for (int k = 0; k < ILP; k++) {
        const unsigned j = jbase + threadIdx.x + (unsigned)k * THREADS;
        const unsigned t = (j >> 4) & 127;
        const bool app = (t == (unsigned)pos);
        const unsigned sidx = app ? (((j >> 11) << 4) | (j & 15))
                                  : (j + delta);
        const float4* __restrict__ src = app ? nbuf : buf;
        r[k] = __ldg(src + sidx);
    }

    // Streaming stores: output never re-read, evict-first.
    #pragma unroll
    for (int k = 0; k < ILP; k++)
        __stcs(out + base + threadIdx.x + (unsigned)k * THREADS, r[k]);
}

extern "C" void kernel_launch(void* const* d_in, const int* in_sizes, int n_in,
                              void* d_out, int out_size)
{
    const float4* kb   = (const float4*)d_in[0];  // k_buf  [L,G,NH,T,HD] fp32
    const float4* vb   = (const float4*)d_in[1];  // v_buf
    const float4* kn   = (const float4*)d_in[2];  // k_new  [L,G,NH,1,HD]
    const float4* vn   = (const float4*)d_in[3];  // v_new
    const int*    beam = (const int*)d_in[4];     // new_beam_idx [G]
    const int*    posp = (const int*)d_in[5];     // pos (scalar, device-side)
    float4*       out  = (float4*)d_out;          // [2,L,G,NH,T,HD] fp32

    const unsigned blocks = TOTAL / (THREADS * ILP);      // 32768
    beam_reorder_append_kernel<<<blocks, THREADS>>>(
        kb, vb, kn, vn, beam, posp, out);
}